// round 2
// baseline (speedup 1.0000x reference)
#include <cuda_runtime.h>
#include <math.h>

#define SS   512
#define BB   256
#define EMBD 128
#define HIDD 256
#define G4   1024   // 4*HID
#define NCLS 8

// ---------------- device scratch (no allocs allowed) ----------------
// xp[d][s][b][4H] : 2*512*256*1024 floats = 1 GB
__device__ float g_xp[(size_t)2 * SS * BB * G4];
// ping-pong hidden state: g_h[buf][d][b][h]
__device__ float g_h[2 * 2 * BB * HIDD];
// final cell state: g_c[d][b][h]
__device__ float g_c[2 * BB * HIDD];
__device__ unsigned g_bar;

// ---------------- init: zero h buffer 0 + barrier counter ----------------
__global__ void k_init() {
    int i = blockIdx.x * blockDim.x + threadIdx.x;
    if (i < 2 * BB * HIDD) g_h[i] = 0.0f;   // buffer 0 only
    if (i == 0) g_bar = 0u;
}

// ---------------- embedding gather + input projection GEMM ----------------
// grid (2048 row-tiles, 16 col-tiles, 2 dirs), 256 threads, 64KB dyn smem
// Row r = s*256 + b  (so each 64-row tile has a single s). Output 64x64 tile.
__global__ void k_xproj(const int* __restrict__ tokens,
                        const float* __restrict__ emb,
                        const float* __restrict__ Wi_f,
                        const float* __restrict__ Wi_b)
{
    extern __shared__ float sh[];
    float* As = sh;              // [128 k][64 row]  (transposed A)
    float* Bs = sh + 128 * 64;   // [128 k][64 col]

    const int d  = blockIdx.z;
    const float* Wi = d ? Wi_b : Wi_f;
    const int r0 = blockIdx.x * 64;
    const int s  = r0 >> 8;
    const int b0 = r0 & 255;
    const int s_tok = d ? (SS - 1 - s) : s;
    const int ct = blockIdx.y;
    const int tid = threadIdx.x;

    // A: 64 rows x 128 cols of embedded tokens, stored transposed
    for (int idx = tid; idx < 64 * 32; idx += 256) {
        int row = idx >> 5;
        int c4  = idx & 31;
        int tok = tokens[(b0 + row) * SS + s_tok];
        float4 v = reinterpret_cast<const float4*>(emb + (size_t)tok * EMBD)[c4];
        int k = c4 * 4;
        As[(k + 0) * 64 + row] = v.x;
        As[(k + 1) * 64 + row] = v.y;
        As[(k + 2) * 64 + row] = v.z;
        As[(k + 3) * 64 + row] = v.w;
    }
    // B: Wi[k][ct*64 + j]
    for (int idx = tid; idx < 128 * 16; idx += 256) {
        int k  = idx >> 4;
        int j4 = idx & 15;
        float4 v = reinterpret_cast<const float4*>(Wi + (size_t)k * G4 + ct * 64)[j4];
        reinterpret_cast<float4*>(Bs + k * 64)[j4] = v;
    }
    __syncthreads();

    const int tx = tid & 15, ty = tid >> 4;
    float acc[4][4];
#pragma unroll
    for (int i = 0; i < 4; i++)
#pragma unroll
        for (int j = 0; j < 4; j++) acc[i][j] = 0.0f;

#pragma unroll 4
    for (int k = 0; k < 128; k++) {
        float4 a = reinterpret_cast<const float4*>(As + k * 64)[ty];
        float4 w = reinterpret_cast<const float4*>(Bs + k * 64)[tx];
        float av[4] = {a.x, a.y, a.z, a.w};
#pragma unroll
        for (int i = 0; i < 4; i++) {
            acc[i][0] += av[i] * w.x;
            acc[i][1] += av[i] * w.y;
            acc[i][2] += av[i] * w.z;
            acc[i][3] += av[i] * w.w;
        }
    }

    const size_t base = (((size_t)d * SS + s) * BB) * G4;
    const int j0 = ct * 64 + tx * 4;
#pragma unroll
    for (int i = 0; i < 4; i++) {
        int b = b0 + ty * 4 + i;
        float4 o = make_float4(acc[i][0], acc[i][1], acc[i][2], acc[i][3]);
        *reinterpret_cast<float4*>(g_xp + base + (size_t)b * G4 + j0) = o;
    }
}

// ---------------- persistent BiLSTM recurrence ----------------
// 256 CTAs x 256 threads, 98816 B dyn smem, occupancy 2 -> all co-resident.
// CTA: d = blk>>7; b-tile of 32 (rem>>4), jh-tile of 16 (rem&15).
// Thread: jj = tid&15 (jh within tile), bg = tid>>4 -> owns 2 b values.
// Each thread owns cells (d, b0+2bg+{0,1}, jh0+jj); c kept in registers.
__global__ void __launch_bounds__(256, 2)
k_lstm(const float* __restrict__ Wh_f, const float* __restrict__ Wh_b,
       const float* __restrict__ b_f,  const float* __restrict__ b_b)
{
    extern __shared__ float sh[];
    float* Wsh = sh;               // [256 k][64 c]; c = jj*4 + g
    float* Ash = sh + 256 * 64;    // [32 row][260]  (padded h tile)

    const int blk = blockIdx.x;
    const int d   = blk >> 7;
    const int rem = blk & 127;
    const int b0  = (rem >> 4) * 32;
    const int jh0 = (rem & 15) * 16;
    const float* Wh   = d ? Wh_b : Wh_f;
    const float* bias = d ? b_b  : b_f;

    const int tid = threadIdx.x;
    const int jj  = tid & 15;
    const int bg  = tid >> 4;
    const int jh  = jh0 + jj;
    const int b_  = b0 + bg * 2;

    // Load Wh columns for this jh-tile once (reused all 512 steps).
    for (int idx = tid; idx < 256 * 64; idx += 256) {
        int k = idx >> 6, c = idx & 63;
        int jjw = c >> 2, g = c & 3;
        Wsh[k * 64 + c] = Wh[(size_t)k * G4 + g * HIDD + jh0 + jjw];
    }
    float bz[4];
#pragma unroll
    for (int g = 0; g < 4; g++) bz[g] = bias[g * HIDD + jh];

    float c0 = 0.0f, c1 = 0.0f;
    const unsigned nb = gridDim.x;
    __syncthreads();

    for (int s = 0; s < SS; s++) {
        const int cur = s & 1;          // read buffer
        const int nxt = cur ^ 1;        // write buffer

        // prefetch xp for this step (independent of smem phase)
        const size_t xbase = (((size_t)d * SS + s) * BB) * G4;
        float xp0[4], xp1[4];
#pragma unroll
        for (int g = 0; g < 4; g++) {
            xp0[g] = g_xp[xbase + (size_t)(b_ + 0) * G4 + g * HIDD + jh];
            xp1[g] = g_xp[xbase + (size_t)(b_ + 1) * G4 + g * HIDD + jh];
        }

        // stage h tile [32 x 256] into shared
        const float4* h4 = reinterpret_cast<const float4*>(
            g_h + ((cur * 2 + d) * BB + b0) * HIDD);
        for (int idx = tid; idx < 32 * 64; idx += 256) {
            int row = idx >> 6, c4 = idx & 63;
            float4 v = h4[row * 64 + c4];
            *reinterpret_cast<float4*>(Ash + row * 260 + c4 * 4) = v;
        }
        __syncthreads();

        // z = h @ Wh  (two b-rows, 4 gate columns each)
        float z0[4] = {0, 0, 0, 0}, z1[4] = {0, 0, 0, 0};
        const float* a0p = Ash + (bg * 2 + 0) * 260;
        const float* a1p = Ash + (bg * 2 + 1) * 260;
        for (int k = 0; k < 256; k += 4) {
            float4 a0 = *reinterpret_cast<const float4*>(a0p + k);
            float4 a1 = *reinterpret_cast<const float4*>(a1p + k);
            float a0v[4] = {a0.x, a0.y, a0.z, a0.w};
            float a1v[4] = {a1.x, a1.y, a1.z, a1.w};
#pragma unroll
            for (int kk = 0; kk < 4; kk++) {
                float4 w = *reinterpret_cast<const float4*>(Wsh + (k + kk) * 64 + jj * 4);
                z0[0] += a0v[kk] * w.x;  z0[1] += a0v[kk] * w.y;
                z0[2] += a0v[kk] * w.z;  z0[3] += a0v[kk] * w.w;
                z1[0] += a1v[kk] * w.x;  z1[1] += a1v[kk] * w.y;
                z1[2] += a1v[kk] * w.z;  z1[3] += a1v[kk] * w.w;
            }
        }

        // gates (order i,f,g,o) + cell update; c stays in registers
        float zi0 = z0[0] + xp0[0] + bz[0];
        float zf0 = z0[1] + xp0[1] + bz[1];
        float zg0 = z0[2] + xp0[2] + bz[2];
        float zo0 = z0[3] + xp0[3] + bz[3];
        float i0 = 1.0f / (1.0f + expf(-zi0));
        float f0 = 1.0f / (1.0f + expf(-zf0));
        float g0 = tanhf(zg0);
        float o0 = 1.0f / (1.0f + expf(-zo0));
        c0 = f0 * c0 + i0 * g0;
        float h0 = o0 * tanhf(c0);

        float zi1 = z1[0] + xp1[0] + bz[0];
        float zf1 = z1[1] + xp1[1] + bz[1];
        float zg1 = z1[2] + xp1[2] + bz[2];
        float zo1 = z1[3] + xp1[3] + bz[3];
        float i1 = 1.0f / (1.0f + expf(-zi1));
        float f1 = 1.0f / (1.0f + expf(-zf1));
        float g1 = tanhf(zg1);
        float o1 = 1.0f / (1.0f + expf(-zo1));
        c1 = f1 * c1 + i1 * g1;
        float h1 = o1 * tanhf(c1);

        // write new h into the other buffer (no race with readers of cur)
        g_h[((nxt * 2 + d) * BB + b_ + 0) * HIDD + jh] = h0;
        g_h[((nxt * 2 + d) * BB + b_ + 1) * HIDD + jh] = h1;

        // grid barrier (counter monotonic within launch; reset by k_init)
        __threadfence();
        __syncthreads();
        if (tid == 0) {
            atomicAdd(&g_bar, 1u);
            const unsigned target = nb * (unsigned)(s + 1);
            while (atomicAdd(&g_bar, 0u) < target) { }
            __threadfence();
        }
        __syncthreads();
    }

    // final cell state out
    g_c[(d * BB + b_ + 0) * HIDD + jh] = c0;
    g_c[(d * BB + b_ + 1) * HIDD + jh] = c1;
}

// ---------------- classifier: [256, 512] @ [512, 8] + bd ----------------
__global__ void k_cls(const float* __restrict__ Wd,
                      const float* __restrict__ bd,
                      float* __restrict__ out)
{
    const int b = blockIdx.x;
    const int t = threadIdx.x;  // 256 threads == H
    float cf = g_c[(0 * BB + b) * HIDD + t];
    float cb = g_c[(1 * BB + b) * HIDD + t];
    float4 w0a = *reinterpret_cast<const float4*>(Wd + t * 8);
    float4 w0b = *reinterpret_cast<const float4*>(Wd + t * 8 + 4);
    float4 w1a = *reinterpret_cast<const float4*>(Wd + (HIDD + t) * 8);
    float4 w1b = *reinterpret_cast<const float4*>(Wd + (HIDD + t) * 8 + 4);

    float p[8];
    p[0] = cf * w0a.x + cb * w1a.x;  p[1] = cf * w0a.y + cb * w1a.y;
    p[2] = cf * w0a.z + cb * w1a.z;  p[3] = cf * w0a.w + cb * w1a.w;
    p[4] = cf * w0b.x + cb * w1b.x;  p[5] = cf * w0b.y + cb * w1b.y;
    p[6] = cf * w0b.z + cb * w1b.z;  p[7] = cf * w0b.w + cb * w1b.w;

#pragma unroll
    for (int n = 0; n < 8; n++)
#pragma unroll
        for (int off = 16; off > 0; off >>= 1)
            p[n] += __shfl_down_sync(0xFFFFFFFFu, p[n], off);

    __shared__ float sm[8][8];
    const int w = t >> 5, lane = t & 31;
    if (lane == 0) {
#pragma unroll
        for (int n = 0; n < 8; n++) sm[w][n] = p[n];
    }
    __syncthreads();
    if (t < NCLS) {
        float sacc = bd[t];
#pragma unroll
        for (int ww = 0; ww < 8; ww++) sacc += sm[ww][t];
        out[b * NCLS + t] = sacc;
    }
}

// ---------------- launch ----------------
extern "C" void kernel_launch(void* const* d_in, const int* in_sizes, int n_in,
                              void* d_out, int out_size)
{
    const int*   tokens = (const int*)  d_in[0];
    const float* emb    = (const float*)d_in[1];
    const float* Wi_f   = (const float*)d_in[2];
    const float* Wh_f   = (const float*)d_in[3];
    const float* b_f    = (const float*)d_in[4];
    const float* Wi_b   = (const float*)d_in[5];
    const float* Wh_b   = (const float*)d_in[6];
    const float* b_b    = (const float*)d_in[7];
    const float* Wd     = (const float*)d_in[8];
    const float* bd     = (const float*)d_in[9];
    float*       out    = (float*)d_out;
    (void)in_sizes; (void)n_in; (void)out_size;

    static bool attr_done = false;
    if (!attr_done) {
        cudaFuncSetAttribute(k_xproj, cudaFuncAttributeMaxDynamicSharedMemorySize, 65536);
        cudaFuncSetAttribute(k_lstm,  cudaFuncAttributeMaxDynamicSharedMemorySize, 98816);
        attr_done = true;
    }

    k_init<<<512, 256>>>();
    k_xproj<<<dim3(2048, 16, 2), 256, 65536>>>(tokens, emb, Wi_f, Wi_b);
    k_lstm<<<256, 256, 98816>>>(Wh_f, Wh_b, b_f, b_b);
    k_cls<<<256, 256>>>(Wd, bd, out);
}

// round 3
// speedup vs baseline: 1.0019x; 1.0019x over previous
#include <cuda_runtime.h>
#include <math.h>

#define SS   512
#define BB   256
#define EMBD 128
#define HIDD 256
#define G4   1024   // 4*HID
#define NCLS 8

// ---------------- device scratch (no allocs allowed) ----------------
// xp[d][s][b][4H] : 2*512*256*1024 floats = 1 GB
__device__ float g_xp[(size_t)2 * SS * BB * G4];
// ping-pong hidden state: g_h[buf][d][b][h]
__device__ float g_h[2 * 2 * BB * HIDD];
// final cell state: g_c[d][b][h]
__device__ float g_c[2 * BB * HIDD];
__device__ unsigned g_bar;

// ---------------- init: zero h buffer 0 + barrier counter ----------------
__global__ void k_init() {
    int i = blockIdx.x * blockDim.x + threadIdx.x;
    if (i < 2 * BB * HIDD) g_h[i] = 0.0f;   // buffer 0 only
    if (i == 0) g_bar = 0u;
}

// ---------------- embedding gather + input projection GEMM ----------------
// grid (2048 row-tiles, 16 col-tiles, 2 dirs), 256 threads, 64KB dyn smem
// Row r = s*256 + b  (so each 64-row tile has a single s). Output 64x64 tile.
__global__ void k_xproj(const int* __restrict__ tokens,
                        const float* __restrict__ emb,
                        const float* __restrict__ Wi_f,
                        const float* __restrict__ Wi_b)
{
    extern __shared__ float sh[];
    float* As = sh;              // [128 k][64 row]  (transposed A)
    float* Bs = sh + 128 * 64;   // [128 k][64 col]

    const int d  = blockIdx.z;
    const float* Wi = d ? Wi_b : Wi_f;
    const int r0 = blockIdx.x * 64;
    const int s  = r0 >> 8;
    const int b0 = r0 & 255;
    const int s_tok = d ? (SS - 1 - s) : s;
    const int ct = blockIdx.y;
    const int tid = threadIdx.x;

    // A: 64 rows x 128 cols of embedded tokens, stored transposed
    for (int idx = tid; idx < 64 * 32; idx += 256) {
        int row = idx >> 5;
        int c4  = idx & 31;
        int tok = tokens[(b0 + row) * SS + s_tok];
        float4 v = reinterpret_cast<const float4*>(emb + (size_t)tok * EMBD)[c4];
        int k = c4 * 4;
        As[(k + 0) * 64 + row] = v.x;
        As[(k + 1) * 64 + row] = v.y;
        As[(k + 2) * 64 + row] = v.z;
        As[(k + 3) * 64 + row] = v.w;
    }
    // B: Wi[k][ct*64 + j]
    for (int idx = tid; idx < 128 * 16; idx += 256) {
        int k  = idx >> 4;
        int j4 = idx & 15;
        float4 v = reinterpret_cast<const float4*>(Wi + (size_t)k * G4 + ct * 64)[j4];
        reinterpret_cast<float4*>(Bs + k * 64)[j4] = v;
    }
    __syncthreads();

    const int tx = tid & 15, ty = tid >> 4;
    float acc[4][4];
#pragma unroll
    for (int i = 0; i < 4; i++)
#pragma unroll
        for (int j = 0; j < 4; j++) acc[i][j] = 0.0f;

#pragma unroll 4
    for (int k = 0; k < 128; k++) {
        float4 a = reinterpret_cast<const float4*>(As + k * 64)[ty];
        float4 w = reinterpret_cast<const float4*>(Bs + k * 64)[tx];
        float av[4] = {a.x, a.y, a.z, a.w};
#pragma unroll
        for (int i = 0; i < 4; i++) {
            acc[i][0] += av[i] * w.x;
            acc[i][1] += av[i] * w.y;
            acc[i][2] += av[i] * w.z;
            acc[i][3] += av[i] * w.w;
        }
    }

    const size_t base = (((size_t)d * SS + s) * BB) * G4;
    const int j0 = ct * 64 + tx * 4;
#pragma unroll
    for (int i = 0; i < 4; i++) {
        int b = b0 + ty * 4 + i;
        float4 o = make_float4(acc[i][0], acc[i][1], acc[i][2], acc[i][3]);
        *reinterpret_cast<float4*>(g_xp + base + (size_t)b * G4 + j0) = o;
    }
}

// ---------------- persistent BiLSTM recurrence ----------------
// 256 CTAs x 256 threads, 98816 B dyn smem, occupancy 2 -> all co-resident.
// CTA: d = blk>>7; b-tile of 32 (rem>>4), jh-tile of 16 (rem&15).
// Thread: jj = tid&15 (jh within tile), bg = tid>>4 -> owns 2 b values.
// Each thread owns cells (d, b0+2bg+{0,1}, jh0+jj); c kept in registers.
__global__ void __launch_bounds__(256, 2)
k_lstm(const float* __restrict__ Wh_f, const float* __restrict__ Wh_b,
       const float* __restrict__ b_f,  const float* __restrict__ b_b)
{
    extern __shared__ float sh[];
    float* Wsh = sh;               // [256 k][64 c]; c = jj*4 + g
    float* Ash = sh + 256 * 64;    // [32 row][260]  (padded h tile)

    const int blk = blockIdx.x;
    const int d   = blk >> 7;
    const int rem = blk & 127;
    const int b0  = (rem >> 4) * 32;
    const int jh0 = (rem & 15) * 16;
    const float* Wh   = d ? Wh_b : Wh_f;
    const float* bias = d ? b_b  : b_f;

    const int tid = threadIdx.x;
    const int jj  = tid & 15;
    const int bg  = tid >> 4;
    const int jh  = jh0 + jj;
    const int b_  = b0 + bg * 2;

    // Load Wh columns for this jh-tile once (reused all 512 steps).
    for (int idx = tid; idx < 256 * 64; idx += 256) {
        int k = idx >> 6, c = idx & 63;
        int jjw = c >> 2, g = c & 3;
        Wsh[k * 64 + c] = Wh[(size_t)k * G4 + g * HIDD + jh0 + jjw];
    }
    float bz[4];
#pragma unroll
    for (int g = 0; g < 4; g++) bz[g] = bias[g * HIDD + jh];

    float c0 = 0.0f, c1 = 0.0f;
    const unsigned nb = gridDim.x;
    __syncthreads();

    for (int s = 0; s < SS; s++) {
        const int cur = s & 1;          // read buffer
        const int nxt = cur ^ 1;        // write buffer

        // prefetch xp for this step (independent of smem phase)
        const size_t xbase = (((size_t)d * SS + s) * BB) * G4;
        float xp0[4], xp1[4];
#pragma unroll
        for (int g = 0; g < 4; g++) {
            xp0[g] = g_xp[xbase + (size_t)(b_ + 0) * G4 + g * HIDD + jh];
            xp1[g] = g_xp[xbase + (size_t)(b_ + 1) * G4 + g * HIDD + jh];
        }

        // stage h tile [32 x 256] into shared
        const float4* h4 = reinterpret_cast<const float4*>(
            g_h + ((cur * 2 + d) * BB + b0) * HIDD);
        for (int idx = tid; idx < 32 * 64; idx += 256) {
            int row = idx >> 6, c4 = idx & 63;
            float4 v = h4[row * 64 + c4];
            *reinterpret_cast<float4*>(Ash + row * 260 + c4 * 4) = v;
        }
        __syncthreads();

        // z = h @ Wh  (two b-rows, 4 gate columns each)
        float z0[4] = {0, 0, 0, 0}, z1[4] = {0, 0, 0, 0};
        const float* a0p = Ash + (bg * 2 + 0) * 260;
        const float* a1p = Ash + (bg * 2 + 1) * 260;
        for (int k = 0; k < 256; k += 4) {
            float4 a0 = *reinterpret_cast<const float4*>(a0p + k);
            float4 a1 = *reinterpret_cast<const float4*>(a1p + k);
            float a0v[4] = {a0.x, a0.y, a0.z, a0.w};
            float a1v[4] = {a1.x, a1.y, a1.z, a1.w};
#pragma unroll
            for (int kk = 0; kk < 4; kk++) {
                float4 w = *reinterpret_cast<const float4*>(Wsh + (k + kk) * 64 + jj * 4);
                z0[0] += a0v[kk] * w.x;  z0[1] += a0v[kk] * w.y;
                z0[2] += a0v[kk] * w.z;  z0[3] += a0v[kk] * w.w;
                z1[0] += a1v[kk] * w.x;  z1[1] += a1v[kk] * w.y;
                z1[2] += a1v[kk] * w.z;  z1[3] += a1v[kk] * w.w;
            }
        }

        // gates (order i,f,g,o) + cell update; c stays in registers
        float zi0 = z0[0] + xp0[0] + bz[0];
        float zf0 = z0[1] + xp0[1] + bz[1];
        float zg0 = z0[2] + xp0[2] + bz[2];
        float zo0 = z0[3] + xp0[3] + bz[3];
        float i0 = 1.0f / (1.0f + expf(-zi0));
        float f0 = 1.0f / (1.0f + expf(-zf0));
        float g0 = tanhf(zg0);
        float o0 = 1.0f / (1.0f + expf(-zo0));
        c0 = f0 * c0 + i0 * g0;
        float h0 = o0 * tanhf(c0);

        float zi1 = z1[0] + xp1[0] + bz[0];
        float zf1 = z1[1] + xp1[1] + bz[1];
        float zg1 = z1[2] + xp1[2] + bz[2];
        float zo1 = z1[3] + xp1[3] + bz[3];
        float i1 = 1.0f / (1.0f + expf(-zi1));
        float f1 = 1.0f / (1.0f + expf(-zf1));
        float g1 = tanhf(zg1);
        float o1 = 1.0f / (1.0f + expf(-zo1));
        c1 = f1 * c1 + i1 * g1;
        float h1 = o1 * tanhf(c1);

        // write new h into the other buffer (no race with readers of cur)
        g_h[((nxt * 2 + d) * BB + b_ + 0) * HIDD + jh] = h0;
        g_h[((nxt * 2 + d) * BB + b_ + 1) * HIDD + jh] = h1;

        // grid barrier (counter monotonic within launch; reset by k_init)
        __threadfence();
        __syncthreads();
        if (tid == 0) {
            atomicAdd(&g_bar, 1u);
            const unsigned target = nb * (unsigned)(s + 1);
            while (atomicAdd(&g_bar, 0u) < target) { }
            __threadfence();
        }
        __syncthreads();
    }

    // final cell state out
    g_c[(d * BB + b_ + 0) * HIDD + jh] = c0;
    g_c[(d * BB + b_ + 1) * HIDD + jh] = c1;
}

// ---------------- classifier: [256, 512] @ [512, 8] + bd ----------------
__global__ void k_cls(const float* __restrict__ Wd,
                      const float* __restrict__ bd,
                      float* __restrict__ out)
{
    const int b = blockIdx.x;
    const int t = threadIdx.x;  // 256 threads == H
    float cf = g_c[(0 * BB + b) * HIDD + t];
    float cb = g_c[(1 * BB + b) * HIDD + t];
    float4 w0a = *reinterpret_cast<const float4*>(Wd + t * 8);
    float4 w0b = *reinterpret_cast<const float4*>(Wd + t * 8 + 4);
    float4 w1a = *reinterpret_cast<const float4*>(Wd + (HIDD + t) * 8);
    float4 w1b = *reinterpret_cast<const float4*>(Wd + (HIDD + t) * 8 + 4);

    float p[8];
    p[0] = cf * w0a.x + cb * w1a.x;  p[1] = cf * w0a.y + cb * w1a.y;
    p[2] = cf * w0a.z + cb * w1a.z;  p[3] = cf * w0a.w + cb * w1a.w;
    p[4] = cf * w0b.x + cb * w1b.x;  p[5] = cf * w0b.y + cb * w1b.y;
    p[6] = cf * w0b.z + cb * w1b.z;  p[7] = cf * w0b.w + cb * w1b.w;

#pragma unroll
    for (int n = 0; n < 8; n++)
#pragma unroll
        for (int off = 16; off > 0; off >>= 1)
            p[n] += __shfl_down_sync(0xFFFFFFFFu, p[n], off);

    __shared__ float sm[8][8];
    const int w = t >> 5, lane = t & 31;
    if (lane == 0) {
#pragma unroll
        for (int n = 0; n < 8; n++) sm[w][n] = p[n];
    }
    __syncthreads();
    if (t < NCLS) {
        float sacc = bd[t];
#pragma unroll
        for (int ww = 0; ww < 8; ww++) sacc += sm[ww][t];
        out[b * NCLS + t] = sacc;
    }
}

// ---------------- launch ----------------
extern "C" void kernel_launch(void* const* d_in, const int* in_sizes, int n_in,
                              void* d_out, int out_size)
{
    const int*   tokens = (const int*)  d_in[0];
    const float* emb    = (const float*)d_in[1];
    const float* Wi_f   = (const float*)d_in[2];
    const float* Wh_f   = (const float*)d_in[3];
    const float* b_f    = (const float*)d_in[4];
    const float* Wi_b   = (const float*)d_in[5];
    const float* Wh_b   = (const float*)d_in[6];
    const float* b_b    = (const float*)d_in[7];
    const float* Wd     = (const float*)d_in[8];
    const float* bd     = (const float*)d_in[9];
    float*       out    = (float*)d_out;
    (void)in_sizes; (void)n_in; (void)out_size;

    static bool attr_done = false;
    if (!attr_done) {
        cudaFuncSetAttribute(k_xproj, cudaFuncAttributeMaxDynamicSharedMemorySize, 65536);
        cudaFuncSetAttribute(k_lstm,  cudaFuncAttributeMaxDynamicSharedMemorySize, 98816);
        attr_done = true;
    }

    k_init<<<512, 256>>>();
    k_xproj<<<dim3(2048, 16, 2), 256, 65536>>>(tokens, emb, Wi_f, Wi_b);
    k_lstm<<<256, 256, 98816>>>(Wh_f, Wh_b, b_f, b_b);
    k_cls<<<256, 256>>>(Wd, bd, out);
}

// round 6
// speedup vs baseline: 1.9565x; 1.9529x over previous
#include <cuda_runtime.h>
#include <cuda_fp16.h>
#include <stdint.h>

#define SS 512
#define BB 256
#define VOC 32000
#define HID 256
#define G4 1024
#define NCLS 8

__device__ float g_eW[(size_t)2 * VOC * G4];                 // [d][v][p], bias baked
__device__ __align__(16) __half g_eh[VOC * 128], g_el[VOC * 128];
__device__ __align__(16) uint32_t g_WiFh[131072], g_WiFl[131072];
__device__ __align__(16) uint32_t g_WhFh[524288], g_WhFl[524288];
__device__ __align__(16) __half g_hh[2 * 2 * BB * HID], g_hl[2 * 2 * BB * HID];
__device__ float g_c[2 * BB * HID];
__device__ unsigned g_bar[4];

__device__ __forceinline__ uint32_t smem_u32(const void* p) {
    uint32_t a;
    asm("{ .reg .u64 t; cvta.to.shared.u64 t, %1; cvt.u32.u64 %0, t; }" : "=r"(a) : "l"(p));
    return a;
}
#define CP16(dst, src) asm volatile("cp.async.cg.shared.global [%0], [%1], 16;" :: "r"(dst), "l"(src))
#define CPCOMMIT() asm volatile("cp.async.commit_group;" ::: "memory")
#define CPWAIT0()  asm volatile("cp.async.wait_group 0;" ::: "memory")

__device__ __forceinline__ void ldsm4(uint32_t addr, uint32_t* r) {
    asm volatile("ldmatrix.sync.aligned.m8n8.x4.shared.b16 {%0,%1,%2,%3}, [%4];"
        : "=r"(r[0]), "=r"(r[1]), "=r"(r[2]), "=r"(r[3]) : "r"(addr));
}
__device__ __forceinline__ void hmma(float* d, const uint32_t* a, const uint32_t* b) {
    asm volatile("mma.sync.aligned.m16n8k16.row.col.f32.f16.f16.f32 "
        "{%0,%1,%2,%3}, {%4,%5,%6,%7}, {%8,%9}, {%0,%1,%2,%3};"
        : "+f"(d[0]), "+f"(d[1]), "+f"(d[2]), "+f"(d[3])
        : "r"(a[0]), "r"(a[1]), "r"(a[2]), "r"(a[3]), "r"(b[0]), "r"(b[1]));
}
__device__ __forceinline__ float sigf(float x) {
    return __fdividef(1.0f, 1.0f + __expf(-x));
}
__device__ __forceinline__ float tanh_(float x) {
    float e = __expf(fminf(2.0f * x, 30.0f));
    return __fdividef(e - 1.0f, e + 1.0f);
}
__device__ __forceinline__ uint32_t packhl(float v0, float v1, int lo) {
    __half h0 = __float2half_rn(v0), h1 = __float2half_rn(v1);
    if (lo) {
        h0 = __float2half_rn(v0 - __half2float(h0));
        h1 = __float2half_rn(v1 - __half2float(h1));
    }
    return ((uint32_t)__half_as_ushort(h1) << 16) | __half_as_ushort(h0);
}

// ---------------- prep ----------------
__global__ void k_prep_emb(const float* __restrict__ emb) {
    int i = blockIdx.x * 256 + threadIdx.x;   // < 4096000
    float v = emb[i];
    __half h = __float2half_rn(v);
    g_eh[i] = h;
    g_el[i] = __float2half_rn(v - __half2float(h));
}
__global__ void k_prep_wif(const float* __restrict__ Wi_f, const float* __restrict__ Wi_b) {
    int i = blockIdx.x * 256 + threadIdx.x;   // < 131072
    int r = i & 1, lane = (i >> 1) & 31, nt = (i >> 6) & 7, ks = (i >> 9) & 7;
    int pt = (i >> 12) & 15, d = (i >> 16) & 1;
    int p = pt * 64 + nt * 8 + (lane >> 2), k0 = ks * 16 + r * 8 + (lane & 3) * 2;
    int col = (p & 3) * HID + (p >> 2);
    const float* W = d ? Wi_b : Wi_f;
    float v0 = W[(size_t)k0 * G4 + col], v1 = W[(size_t)(k0 + 1) * G4 + col];
    g_WiFh[i] = packhl(v0, v1, 0);
    g_WiFl[i] = packhl(v0, v1, 1);
}
__global__ void k_prep_whf(const float* __restrict__ Wh_f, const float* __restrict__ Wh_b) {
    int i = blockIdx.x * 256 + threadIdx.x;   // < 524288
    int r = i & 1, lane = (i >> 1) & 31, nt = (i >> 6) & 7, ks = (i >> 9) & 15;
    int jt = (i >> 13) & 15, d = (i >> 17) & 1;
    int p = jt * 64 + nt * 8 + (lane >> 2), k0 = ks * 16 + r * 8 + (lane & 3) * 2;
    int col = (p & 3) * HID + (p >> 2);
    const float* W = d ? Wh_b : Wh_f;
    float v0 = W[(size_t)k0 * G4 + col], v1 = W[(size_t)(k0 + 1) * G4 + col];
    g_WhFh[i] = packhl(v0, v1, 0);
    g_WhFl[i] = packhl(v0, v1, 1);
}
__global__ void k_init() {
    int i = blockIdx.x * 256 + threadIdx.x;   // 65536: buffer 0 of g_hh/g_hl
    ((uint32_t*)g_hh)[i] = 0u;
    ((uint32_t*)g_hl)[i] = 0u;
    if (i < 4) g_bar[i] = 0u;
}

// ---------------- xproj: eW = emb @ Wi (3-pass fp16 HMMA) + bias ----------------
#define XRS 272
__global__ void __launch_bounds__(256, 1)
k_xproj(const float* __restrict__ bf_, const float* __restrict__ bb_) {
    extern __shared__ __align__(16) char sm[];
    const uint32_t sb = smem_u32(sm);
    const int tid = threadIdx.x, lane = tid & 31, w = tid >> 5, wm = w >> 1, wn = w & 1;
    const int d = blockIdx.z, pt = blockIdx.y, v0 = blockIdx.x * 128;

    for (int i = tid; i < 128 * 16; i += 256) {
        int r = i >> 4, kb = (i & 15) * 16;
        CP16(sb + r * XRS + kb, (const char*)(g_eh + (size_t)(v0 + r) * 128) + kb);
        CP16(sb + 34816 + r * XRS + kb, (const char*)(g_el + (size_t)(v0 + r) * 128) + kb);
    }
    CPCOMMIT(); CPWAIT0();
    __syncthreads();

    float acc[32];
#pragma unroll
    for (int i = 0; i < 32; i++) acc[i] = 0.0f;
    const uint32_t aH = sb + (wm * 32 + (lane & 15)) * XRS + ((lane >> 4) * 8) * 2;
    const uint2* Bh = (const uint2*)g_WiFh + (d * 16 + pt) * 2048;
    const uint2* Bl = (const uint2*)g_WiFl + (d * 16 + pt) * 2048;

#pragma unroll
    for (int ks = 0; ks < 8; ks++) {
        uint32_t ah[8], al[8];
        ldsm4(aH + ks * 32, ah);
        ldsm4(aH + 16 * XRS + ks * 32, ah + 4);
        ldsm4(aH + 34816 + ks * 32, al);
        ldsm4(aH + 34816 + 16 * XRS + ks * 32, al + 4);
#pragma unroll
        for (int nt = 0; nt < 4; nt++) {
            int ntg = wn * 4 + nt;
            uint2 bh = __ldg(Bh + (ks * 8 + ntg) * 32 + lane);
            uint2 bl = __ldg(Bl + (ks * 8 + ntg) * 32 + lane);
#pragma unroll
            for (int mt = 0; mt < 2; mt++) {
                float* a = acc + (mt * 4 + nt) * 4;
                hmma(a, ah + mt * 4, (const uint32_t*)&bh);
                hmma(a, al + mt * 4, (const uint32_t*)&bh);
                hmma(a, ah + mt * 4, (const uint32_t*)&bl);
            }
        }
    }
    const float* bias = d ? bb_ : bf_;
#pragma unroll
    for (int mt = 0; mt < 2; mt++)
#pragma unroll
        for (int nt = 0; nt < 4; nt++) {
            int pc = pt * 64 + (wn * 4 + nt) * 8 + (lane & 3) * 2;
            float b0v = bias[(pc & 3) * HID + (pc >> 2)];
            float b1v = bias[((pc + 1) & 3) * HID + ((pc + 1) >> 2)];
            int v = v0 + wm * 32 + mt * 16 + (lane >> 2);
            float* a = acc + (mt * 4 + nt) * 4;
            *(float2*)(g_eW + ((size_t)d * VOC + v) * G4 + pc) = make_float2(a[0] + b0v, a[1] + b1v);
            *(float2*)(g_eW + ((size_t)d * VOC + v + 8) * G4 + pc) = make_float2(a[2] + b0v, a[3] + b1v);
        }
}

// ---------------- persistent recurrence: 64 CTAs x 256 thr ----------------
#define LRS 528
#define LAL 67584
#define LBH 135168
#define LBL 167936
#define LTK 200704
#define LSZ 201216
__global__ void __launch_bounds__(256, 1)
k_lstm(const int* __restrict__ tokens) {
    extern __shared__ __align__(16) char sm[];
    const uint32_t sb = smem_u32(sm);
    uint32_t* sBH = (uint32_t*)(sm + LBH);
    uint32_t* sBL = (uint32_t*)(sm + LBL);
    int* stok = (int*)(sm + LTK);
    const int tid = threadIdx.x, lane = tid & 31, w = tid >> 5, wm = w >> 1, wn = w & 1;
    const int bi = blockIdx.x, d = bi >> 5, bt = (bi >> 4) & 1, jt = bi & 15;
    const int b0 = bt * 128, grp = d * 2 + bt;

    {   // Wh fragments resident in smem for all 512 steps
        const uint4* sh = (const uint4*)(g_WhFh + (d * 16 + jt) * 8192);
        const uint4* sl = (const uint4*)(g_WhFl + (d * 16 + jt) * 8192);
        for (int i = tid; i < 2048; i += 256) {
            ((uint4*)sBH)[i] = sh[i];
            ((uint4*)sBL)[i] = sl[i];
        }
    }
    float cc[8];
#pragma unroll
    for (int f = 0; f < 8; f++) cc[f] = 0.0f;
    const uint32_t aH = sb + (wm * 32 + (lane & 15)) * LRS + ((lane >> 4) * 8) * 2;
    __syncthreads();

    for (int s = 0; s < SS; s++) {
        const int cur = s & 1, nxt = cur ^ 1;
        const int sd = d ? (SS - 1 - s) : s;
        if (tid < 128) stok[tid] = __ldg(tokens + (size_t)(b0 + tid) * SS + sd);

        const char* hsh = (const char*)(g_hh + ((size_t)(cur * 2 + d) * BB + b0) * HID);
        const char* hsl = (const char*)(g_hl + ((size_t)(cur * 2 + d) * BB + b0) * HID);
        for (int i = tid; i < 128 * 32; i += 256) {
            int r = i >> 5, kb = (i & 31) * 16;
            CP16(sb + r * LRS + kb, hsh + r * 512 + kb);
            CP16(sb + LAL + r * LRS + kb, hsl + r * 512 + kb);
        }
        CPCOMMIT();
        __syncthreads();   // stok visible

        float acc[32];
#pragma unroll
        for (int mt = 0; mt < 2; mt++)
#pragma unroll
            for (int nt = 0; nt < 4; nt++) {
                int pc = jt * 64 + (wn * 4 + nt) * 8 + (lane & 3) * 2;
                int r1 = wm * 32 + mt * 16 + (lane >> 2);
                int t1 = stok[r1], t2 = stok[r1 + 8];
                float2 x1 = *(const float2*)(g_eW + ((size_t)d * VOC + t1) * G4 + pc);
                float2 x2 = *(const float2*)(g_eW + ((size_t)d * VOC + t2) * G4 + pc);
                float* a = acc + (mt * 4 + nt) * 4;
                a[0] = x1.x; a[1] = x1.y; a[2] = x2.x; a[3] = x2.y;
            }
        CPWAIT0();
        __syncthreads();

#pragma unroll 4
        for (int ks = 0; ks < 16; ks++) {
            uint32_t ah[8], al[8];
            ldsm4(aH + ks * 32, ah);
            ldsm4(aH + 16 * LRS + ks * 32, ah + 4);
            ldsm4(aH + LAL + ks * 32, al);
            ldsm4(aH + LAL + 16 * LRS + ks * 32, al + 4);
#pragma unroll
            for (int nt = 0; nt < 4; nt++) {
                int ntg = wn * 4 + nt;
                uint2 bh = *(const uint2*)(sBH + ((ks * 8 + ntg) * 32 + lane) * 2);
                uint2 bl = *(const uint2*)(sBL + ((ks * 8 + ntg) * 32 + lane) * 2);
#pragma unroll
                for (int mt = 0; mt < 2; mt++) {
                    float* a = acc + (mt * 4 + nt) * 4;
                    hmma(a, ah + mt * 4, (const uint32_t*)&bh);
                    hmma(a, al + mt * 4, (const uint32_t*)&bh);
                    hmma(a, ah + mt * 4, (const uint32_t*)&bl);
                }
            }
        }
        // epilogue: gate exchange within lane pairs, cell update, h write
#pragma unroll
        for (int f = 0; f < 8; f++) {
            float* a = acc + f * 4;
            float s0 = (lane & 1) ? a[0] : a[2];
            float s1 = (lane & 1) ? a[1] : a[3];
            float r0 = __shfl_xor_sync(0xFFFFFFFFu, s0, 1);
            float r1 = __shfl_xor_sync(0xFFFFFFFFu, s1, 1);
            float zi, zf, zg, zo;
            if (lane & 1) { zi = r0; zf = r1; zg = a[2]; zo = a[3]; }
            else          { zi = a[0]; zf = a[1]; zg = r0; zo = r1; }
            float ii = sigf(zi), ff = sigf(zf), gg = tanh_(zg), oo = sigf(zo);
            cc[f] = ff * cc[f] + ii * gg;
            float h = oo * tanh_(cc[f]);
            int mt = f >> 2, nt = f & 3;
            int row = wm * 32 + mt * 16 + (lane >> 2) + ((lane & 1) ? 8 : 0);
            int j = jt * 16 + (wn * 4 + nt) * 2 + ((lane & 2) ? 1 : 0);
            __half hh = __float2half_rn(h);
            size_t o = ((size_t)(nxt * 2 + d) * BB + b0 + row) * HID + j;
            g_hh[o] = hh;
            g_hl[o] = __float2half_rn(h - __half2float(hh));
        }
        __threadfence();
        __syncthreads();
        if (tid == 0) {
            atomicAdd(&g_bar[grp], 1u);
            const unsigned tgt = 16u * (unsigned)(s + 1);
            while (atomicAdd(&g_bar[grp], 0u) < tgt) { }
            __threadfence();
        }
        __syncthreads();
    }
#pragma unroll
    for (int f = 0; f < 8; f++) {
        int mt = f >> 2, nt = f & 3;
        int row = wm * 32 + mt * 16 + (lane >> 2) + ((lane & 1) ? 8 : 0);
        int j = jt * 16 + (wn * 4 + nt) * 2 + ((lane & 2) ? 1 : 0);
        g_c[((size_t)d * BB + b0 + row) * HID + j] = cc[f];
    }
}

// ---------------- classifier ----------------
__global__ void k_cls(const float* __restrict__ Wd, const float* __restrict__ bd,
                      float* __restrict__ out) {
    const int b = blockIdx.x, t = threadIdx.x;
    float cf = g_c[(size_t)(0 * BB + b) * HID + t];
    float cb = g_c[(size_t)(1 * BB + b) * HID + t];
    float p[8];
#pragma unroll
    for (int n = 0; n < 8; n++)
        p[n] = cf * Wd[t * NCLS + n] + cb * Wd[(HID + t) * NCLS + n];
#pragma unroll
    for (int n = 0; n < 8; n++)
#pragma unroll
        for (int off = 16; off > 0; off >>= 1)
            p[n] += __shfl_down_sync(0xFFFFFFFFu, p[n], off);
    __shared__ float smc[8][8];
    const int wi = t >> 5, lane = t & 31;
    if (lane == 0) {
#pragma unroll
        for (int n = 0; n < 8; n++) smc[wi][n] = p[n];
    }
    __syncthreads();
    if (t < NCLS) {
        float a = bd[t];
#pragma unroll
        for (int ww = 0; ww < 8; ww++) a += smc[ww][t];
        out[b * NCLS + t] = a;
    }
}

// ---------------- launch ----------------
extern "C" void kernel_launch(void* const* d_in, const int* in_sizes, int n_in,
                              void* d_out, int out_size) {
    const int*   tokens = (const int*)  d_in[0];
    const float* emb    = (const float*)d_in[1];
    const float* Wi_f   = (const float*)d_in[2];
    const float* Wh_f   = (const float*)d_in[3];
    const float* b_f    = (const float*)d_in[4];
    const float* Wi_b   = (const float*)d_in[5];
    const float* Wh_b   = (const float*)d_in[6];
    const float* b_b    = (const float*)d_in[7];
    const float* Wd     = (const float*)d_in[8];
    const float* bd     = (const float*)d_in[9];
    float*       out    = (float*)d_out;
    (void)in_sizes; (void)n_in; (void)out_size;

    static bool done = false;
    if (!done) {
        cudaFuncSetAttribute(k_xproj, cudaFuncAttributeMaxDynamicSharedMemorySize, 69632);
        cudaFuncSetAttribute(k_lstm,  cudaFuncAttributeMaxDynamicSharedMemorySize, LSZ);
        done = true;
    }
    k_prep_emb<<<16000, 256>>>(emb);
    k_prep_wif<<<512, 256>>>(Wi_f, Wi_b);
    k_prep_whf<<<2048, 256>>>(Wh_f, Wh_b);
    k_init<<<256, 256>>>();
    k_xproj<<<dim3(250, 16, 2), 256, 69632>>>(b_f, b_b);
    k_lstm<<<64, 256, LSZ>>>(tokens);
    k_cls<<<256, 256>>>(Wd, bd, out);
}

// round 7
// speedup vs baseline: 3.3525x; 1.7135x over previous
#include <cuda_runtime.h>
#include <cuda_fp16.h>
#include <stdint.h>

#define SS 512
#define BB 256
#define VOC 32000
#define HID 256
#define G4 1024
#define NCLS 8

__device__ float g_eW[(size_t)2 * VOC * G4];                 // [d][v][p], bias baked
__device__ __align__(16) __half g_eh[VOC * 128], g_el[VOC * 128];
__device__ __align__(16) uint32_t g_WiFh[131072], g_WiFl[131072];
__device__ __align__(16) uint32_t g_WhFh[524288], g_WhFl[524288];
__device__ __align__(16) __half g_hh[2 * 2 * BB * HID], g_hl[2 * 2 * BB * HID];
__device__ float g_c[2 * BB * HID];
__device__ unsigned g_bar[8];

__device__ __forceinline__ uint32_t smem_u32(const void* p) {
    uint32_t a;
    asm("{ .reg .u64 t; cvta.to.shared.u64 t, %1; cvt.u32.u64 %0, t; }" : "=r"(a) : "l"(p));
    return a;
}
#define CP16(dst, src) asm volatile("cp.async.cg.shared.global [%0], [%1], 16;" :: "r"(dst), "l"(src))
#define CPCOMMIT() asm volatile("cp.async.commit_group;" ::: "memory")
#define CPWAIT0()  asm volatile("cp.async.wait_group 0;" ::: "memory")

__device__ __forceinline__ void ldsm4(uint32_t addr, uint32_t* r) {
    asm volatile("ldmatrix.sync.aligned.m8n8.x4.shared.b16 {%0,%1,%2,%3}, [%4];"
        : "=r"(r[0]), "=r"(r[1]), "=r"(r[2]), "=r"(r[3]) : "r"(addr));
}
__device__ __forceinline__ void hmma(float* d, const uint32_t* a, const uint32_t* b) {
    asm volatile("mma.sync.aligned.m16n8k16.row.col.f32.f16.f16.f32 "
        "{%0,%1,%2,%3}, {%4,%5,%6,%7}, {%8,%9}, {%0,%1,%2,%3};"
        : "+f"(d[0]), "+f"(d[1]), "+f"(d[2]), "+f"(d[3])
        : "r"(a[0]), "r"(a[1]), "r"(a[2]), "r"(a[3]), "r"(b[0]), "r"(b[1]));
}
__device__ __forceinline__ float sigf(float x) {
    return __fdividef(1.0f, 1.0f + __expf(-x));
}
__device__ __forceinline__ float tanh_(float x) {
    float e = __expf(fminf(2.0f * x, 30.0f));
    return __fdividef(e - 1.0f, e + 1.0f);
}
__device__ __forceinline__ uint32_t packhl(float v0, float v1, int lo) {
    __half h0 = __float2half_rn(v0), h1 = __float2half_rn(v1);
    if (lo) {
        h0 = __float2half_rn(v0 - __half2float(h0));
        h1 = __float2half_rn(v1 - __half2float(h1));
    }
    return ((uint32_t)__half_as_ushort(h1) << 16) | __half_as_ushort(h0);
}

// ---------------- prep ----------------
__global__ void k_prep_emb(const float* __restrict__ emb) {
    int i = blockIdx.x * 256 + threadIdx.x;   // < 4096000
    float v = emb[i];
    __half h = __float2half_rn(v);
    g_eh[i] = h;
    g_el[i] = __float2half_rn(v - __half2float(h));
}
__global__ void k_prep_wif(const float* __restrict__ Wi_f, const float* __restrict__ Wi_b) {
    int i = blockIdx.x * 256 + threadIdx.x;   // < 131072
    int r = i & 1, lane = (i >> 1) & 31, nt = (i >> 6) & 7, ks = (i >> 9) & 7;
    int pt = (i >> 12) & 15, d = (i >> 16) & 1;
    int p = pt * 64 + nt * 8 + (lane >> 2), k0 = ks * 16 + r * 8 + (lane & 3) * 2;
    int col = (p & 3) * HID + (p >> 2);
    const float* W = d ? Wi_b : Wi_f;
    float v0 = W[(size_t)k0 * G4 + col], v1 = W[(size_t)(k0 + 1) * G4 + col];
    g_WiFh[i] = packhl(v0, v1, 0);
    g_WiFl[i] = packhl(v0, v1, 1);
}
__global__ void k_prep_whf(const float* __restrict__ Wh_f, const float* __restrict__ Wh_b) {
    int i = blockIdx.x * 256 + threadIdx.x;   // < 524288
    int r = i & 1, lane = (i >> 1) & 31, nt = (i >> 6) & 7, ks = (i >> 9) & 15;
    int jt = (i >> 13) & 15, d = (i >> 17) & 1;
    int p = jt * 64 + nt * 8 + (lane >> 2), k0 = ks * 16 + r * 8 + (lane & 3) * 2;
    int col = (p & 3) * HID + (p >> 2);
    const float* W = d ? Wh_b : Wh_f;
    float v0 = W[(size_t)k0 * G4 + col], v1 = W[(size_t)(k0 + 1) * G4 + col];
    g_WhFh[i] = packhl(v0, v1, 0);
    g_WhFl[i] = packhl(v0, v1, 1);
}
__global__ void k_init() {
    int i = blockIdx.x * 256 + threadIdx.x;   // 65536: buffer 0 of g_hh/g_hl
    ((uint32_t*)g_hh)[i] = 0u;
    ((uint32_t*)g_hl)[i] = 0u;
    if (i < 8) g_bar[i] = 0u;
}

// ---------------- xproj: eW = emb @ Wi (3-pass fp16 HMMA) + bias ----------------
#define XRS 272
__global__ void __launch_bounds__(256, 1)
k_xproj(const float* __restrict__ bf_, const float* __restrict__ bb_) {
    extern __shared__ __align__(16) char sm[];
    const uint32_t sb = smem_u32(sm);
    const int tid = threadIdx.x, lane = tid & 31, w = tid >> 5, wm = w >> 1, wn = w & 1;
    const int d = blockIdx.z, pt = blockIdx.y, v0 = blockIdx.x * 128;

    for (int i = tid; i < 128 * 16; i += 256) {
        int r = i >> 4, kb = (i & 15) * 16;
        CP16(sb + r * XRS + kb, (const char*)(g_eh + (size_t)(v0 + r) * 128) + kb);
        CP16(sb + 34816 + r * XRS + kb, (const char*)(g_el + (size_t)(v0 + r) * 128) + kb);
    }
    CPCOMMIT(); CPWAIT0();
    __syncthreads();

    float acc[32];
#pragma unroll
    for (int i = 0; i < 32; i++) acc[i] = 0.0f;
    const uint32_t aH = sb + (wm * 32 + (lane & 15)) * XRS + ((lane >> 4) * 8) * 2;
    const uint2* Bh = (const uint2*)g_WiFh + (d * 16 + pt) * 2048;
    const uint2* Bl = (const uint2*)g_WiFl + (d * 16 + pt) * 2048;

#pragma unroll
    for (int ks = 0; ks < 8; ks++) {
        uint32_t ah[8], al[8];
        ldsm4(aH + ks * 32, ah);
        ldsm4(aH + 16 * XRS + ks * 32, ah + 4);
        ldsm4(aH + 34816 + ks * 32, al);
        ldsm4(aH + 34816 + 16 * XRS + ks * 32, al + 4);
#pragma unroll
        for (int nt = 0; nt < 4; nt++) {
            int ntg = wn * 4 + nt;
            uint2 bh = __ldg(Bh + (ks * 8 + ntg) * 32 + lane);
            uint2 bl = __ldg(Bl + (ks * 8 + ntg) * 32 + lane);
#pragma unroll
            for (int mt = 0; mt < 2; mt++) {
                float* a = acc + (mt * 4 + nt) * 4;
                hmma(a, ah + mt * 4, (const uint32_t*)&bh);
                hmma(a, al + mt * 4, (const uint32_t*)&bh);
                hmma(a, ah + mt * 4, (const uint32_t*)&bl);
            }
        }
    }
    const float* bias = d ? bb_ : bf_;
#pragma unroll
    for (int mt = 0; mt < 2; mt++)
#pragma unroll
        for (int nt = 0; nt < 4; nt++) {
            int pc = pt * 64 + (wn * 4 + nt) * 8 + (lane & 3) * 2;
            float b0v = bias[(pc & 3) * HID + (pc >> 2)];
            float b1v = bias[((pc + 1) & 3) * HID + ((pc + 1) >> 2)];
            int v = v0 + wm * 32 + mt * 16 + (lane >> 2);
            float* a = acc + (mt * 4 + nt) * 4;
            *(float2*)(g_eW + ((size_t)d * VOC + v) * G4 + pc) = make_float2(a[0] + b0v, a[1] + b1v);
            *(float2*)(g_eW + ((size_t)d * VOC + v + 8) * G4 + pc) = make_float2(a[2] + b0v, a[3] + b1v);
        }
}

// ---------------- persistent recurrence: 128 CTAs x 256 thr ----------------
// CTA: d = bi>>6, bq = (bi>>4)&3 (batch quarter, 64 rows), jt = bi&15 (16 j-cols).
// 8 groups of 16 CTAs; M=64, N=64, K=256 per step per CTA.
#define LRS 528
#define A_LO 33792
#define B_HI 67584
#define B_LO 100352
#define LSZ  133120
__global__ void __launch_bounds__(256, 1)
k_lstm(const int* __restrict__ tokens) {
    extern __shared__ __align__(16) char sm[];
    const uint32_t sb = smem_u32(sm);
    uint32_t* sBH = (uint32_t*)(sm + B_HI);
    uint32_t* sBL = (uint32_t*)(sm + B_LO);
    const int tid = threadIdx.x, lane = tid & 31, w = tid >> 5, wm = w >> 1, wn = w & 1;
    const int bi = blockIdx.x, d = bi >> 6, bq = (bi >> 4) & 3, jt = bi & 15;
    const int b0 = bq * 64, grp = d * 4 + bq;

    {   // Wh fragments resident in smem for all 512 steps (32KB hi + 32KB lo)
        const uint4* shsrc = (const uint4*)(g_WhFh + (d * 16 + jt) * 8192);
        const uint4* slsrc = (const uint4*)(g_WhFl + (d * 16 + jt) * 8192);
        for (int i = tid; i < 2048; i += 256) {
            ((uint4*)sBH)[i] = shsrc[i];
            ((uint4*)sBL)[i] = slsrc[i];
        }
    }
    float cc[4];
#pragma unroll
    for (int f = 0; f < 4; f++) cc[f] = 0.0f;
    const uint32_t aH = sb + (wm * 16 + (lane & 15)) * LRS + ((lane >> 4) * 8) * 2;
    const int r1 = wm * 16 + (lane >> 2);

    // prefetch step-0 tokens into registers
    int sd0 = d ? (SS - 1) : 0;
    int tk0 = __ldg(tokens + (size_t)(b0 + r1) * SS + sd0);
    int tk1 = __ldg(tokens + (size_t)(b0 + r1 + 8) * SS + sd0);
    __syncthreads();

    for (int s = 0; s < SS; s++) {
        const int cur = s & 1, nxt = cur ^ 1;

        // stage h tile (64 rows x 512B, hi+lo) via cp.async into padded rows
        const char* hsh = (const char*)(g_hh + ((size_t)(cur * 2 + d) * BB + b0) * HID);
        const char* hsl = (const char*)(g_hl + ((size_t)(cur * 2 + d) * BB + b0) * HID);
        for (int i = tid; i < 64 * 32; i += 256) {
            int r = i >> 5, kb = (i & 31) * 16;
            CP16(sb + r * LRS + kb, hsh + r * 512 + kb);
            CP16(sb + A_LO + r * LRS + kb, hsl + r * 512 + kb);
        }
        CPCOMMIT();

        // gather xp from eW directly into accumulators (overlaps staging)
        float acc[16];
#pragma unroll
        for (int nt = 0; nt < 4; nt++) {
            int pc = jt * 64 + (wn * 4 + nt) * 8 + (lane & 3) * 2;
            float2 x1 = *(const float2*)(g_eW + ((size_t)d * VOC + tk0) * G4 + pc);
            float2 x2 = *(const float2*)(g_eW + ((size_t)d * VOC + tk1) * G4 + pc);
            acc[nt * 4 + 0] = x1.x; acc[nt * 4 + 1] = x1.y;
            acc[nt * 4 + 2] = x2.x; acc[nt * 4 + 3] = x2.y;
        }
        // prefetch next step's tokens (hidden under MMA)
        {
            int sn = (s + 1 < SS) ? s + 1 : 0;
            int sdn = d ? (SS - 1 - sn) : sn;
            tk0 = __ldg(tokens + (size_t)(b0 + r1) * SS + sdn);
            tk1 = __ldg(tokens + (size_t)(b0 + r1 + 8) * SS + sdn);
        }
        CPWAIT0();
        __syncthreads();

#pragma unroll 4
        for (int ks = 0; ks < 16; ks++) {
            uint32_t ah[4], al[4];
            ldsm4(aH + ks * 32, ah);
            ldsm4(aH + A_LO + ks * 32, al);
#pragma unroll
            for (int nt = 0; nt < 4; nt++) {
                int ntg = wn * 4 + nt;
                uint2 bh = *(const uint2*)(sBH + ((ks * 8 + ntg) * 32 + lane) * 2);
                uint2 bl = *(const uint2*)(sBL + ((ks * 8 + ntg) * 32 + lane) * 2);
                float* a = acc + nt * 4;
                hmma(a, ah, (const uint32_t*)&bh);
                hmma(a, al, (const uint32_t*)&bh);
                hmma(a, ah, (const uint32_t*)&bl);
            }
        }

        // epilogue: gate exchange within lane pairs, cell update, h write
#pragma unroll
        for (int nt = 0; nt < 4; nt++) {
            float* a = acc + nt * 4;
            float s0 = (lane & 1) ? a[0] : a[2];
            float s1 = (lane & 1) ? a[1] : a[3];
            float q0 = __shfl_xor_sync(0xFFFFFFFFu, s0, 1);
            float q1 = __shfl_xor_sync(0xFFFFFFFFu, s1, 1);
            float zi, zf, zg, zo;
            if (lane & 1) { zi = q0; zf = q1; zg = a[2]; zo = a[3]; }
            else          { zi = a[0]; zf = a[1]; zg = q0; zo = q1; }
            float ii = sigf(zi), ff = sigf(zf), gg = tanh_(zg), oo = sigf(zo);
            cc[nt] = ff * cc[nt] + ii * gg;
            float h = oo * tanh_(cc[nt]);
            int row = wm * 16 + (lane >> 2) + ((lane & 1) ? 8 : 0);
            int j = jt * 16 + (wn * 4 + nt) * 2 + ((lane & 2) ? 1 : 0);
            __half hh = __float2half_rn(h);
            size_t o = ((size_t)(nxt * 2 + d) * BB + b0 + row) * HID + j;
            g_hh[o] = hh;
            g_hl[o] = __float2half_rn(h - __half2float(hh));
        }

        // group barrier: release-RED arrive + acquire-LD poll (16 CTAs per group)
        __syncthreads();
        if (tid == 0) {
            const unsigned tgt = 16u * (unsigned)(s + 1);
            asm volatile("red.release.gpu.add.u32 [%0], 1;" :: "l"(g_bar + grp) : "memory");
            unsigned v;
            do {
                asm volatile("ld.acquire.gpu.b32 %0, [%1];" : "=r"(v) : "l"(g_bar + grp) : "memory");
            } while (v < tgt);
        }
        __syncthreads();
    }
#pragma unroll
    for (int nt = 0; nt < 4; nt++) {
        int row = wm * 16 + (lane >> 2) + ((lane & 1) ? 8 : 0);
        int j = jt * 16 + (wn * 4 + nt) * 2 + ((lane & 2) ? 1 : 0);
        g_c[((size_t)d * BB + b0 + row) * HID + j] = cc[nt];
    }
}

// ---------------- classifier ----------------
__global__ void k_cls(const float* __restrict__ Wd, const float* __restrict__ bd,
                      float* __restrict__ out) {
    const int b = blockIdx.x, t = threadIdx.x;
    float cf = g_c[(size_t)(0 * BB + b) * HID + t];
    float cb = g_c[(size_t)(1 * BB + b) * HID + t];
    float p[8];
#pragma unroll
    for (int n = 0; n < 8; n++)
        p[n] = cf * Wd[t * NCLS + n] + cb * Wd[(HID + t) * NCLS + n];
#pragma unroll
    for (int n = 0; n < 8; n++)
#pragma unroll
        for (int off = 16; off > 0; off >>= 1)
            p[n] += __shfl_down_sync(0xFFFFFFFFu, p[n], off);
    __shared__ float smc[8][8];
    const int wi = t >> 5, lane = t & 31;
    if (lane == 0) {
#pragma unroll
        for (int n = 0; n < 8; n++) smc[wi][n] = p[n];
    }
    __syncthreads();
    if (t < NCLS) {
        float a = bd[t];
#pragma unroll
        for (int ww = 0; ww < 8; ww++) a += smc[ww][t];
        out[b * NCLS + t] = a;
    }
}

// ---------------- launch ----------------
extern "C" void kernel_launch(void* const* d_in, const int* in_sizes, int n_in,
                              void* d_out, int out_size) {
    const int*   tokens = (const int*)  d_in[0];
    const float* emb    = (const float*)d_in[1];
    const float* Wi_f   = (const float*)d_in[2];
    const float* Wh_f   = (const float*)d_in[3];
    const float* b_f    = (const float*)d_in[4];
    const float* Wi_b   = (const float*)d_in[5];
    const float* Wh_b   = (const float*)d_in[6];
    const float* b_b    = (const float*)d_in[7];
    const float* Wd     = (const float*)d_in[8];
    const float* bd     = (const float*)d_in[9];
    float*       out    = (float*)d_out;
    (void)in_sizes; (void)n_in; (void)out_size;

    static bool done = false;
    if (!done) {
        cudaFuncSetAttribute(k_xproj, cudaFuncAttributeMaxDynamicSharedMemorySize, 69632);
        cudaFuncSetAttribute(k_lstm,  cudaFuncAttributeMaxDynamicSharedMemorySize, LSZ);
        done = true;
    }
    k_prep_emb<<<16000, 256>>>(emb);
    k_prep_wif<<<512, 256>>>(Wi_f, Wi_b);
    k_prep_whf<<<2048, 256>>>(Wh_f, Wh_b);
    k_init<<<256, 256>>>();
    k_xproj<<<dim3(250, 16, 2), 256, 69632>>>(b_f, b_b);
    k_lstm<<<128, 256, LSZ>>>(tokens);
    k_cls<<<256, 256>>>(Wd, bd, out);
}